// round 5
// baseline (speedup 1.0000x reference)
#include <cuda_runtime.h>

#define NROWS 65536
#define DDATA 512
#define DLAT  64
#define KC    64
#define TILE  64
#define NT    256
#define NBLK  (NROWS / TILE)     // 1024
#define NITER 10
#define EPSV  1e-8f
#define ALPHA 0.001f

#define XP 68
#define RP 68
#define CP 68

typedef unsigned long long ull;

struct AccBuf { float acc[KC * DLAT]; float cs[KC]; };
__device__ AccBuf g_acc[3];
struct LossBuf { float loss; float pad; double dloss; };
__device__ LossBuf g_l;

__device__ __forceinline__ ull pack2(float a, float b) {
    ull r; asm("mov.b64 %0, {%1, %2};" : "=l"(r) : "f"(a), "f"(b)); return r;
}
__device__ __forceinline__ void unpack2(ull v, float& a, float& b) {
    asm("mov.b64 {%0, %1}, %2;" : "=f"(a), "=f"(b) : "l"(v));
}
__device__ __forceinline__ ull ffma2(ull a, ull b, ull c) {
    ull d; asm("fma.rn.f32x2 %0, %1, %2, %3;" : "=l"(d) : "l"(a), "l"(b), "l"(c)); return d;
}
__device__ __forceinline__ ull add2(ull a, ull b) {
    ull d; asm("add.rn.f32x2 %0, %1, %2;" : "=l"(d) : "l"(a), "l"(b)); return d;
}
__device__ __forceinline__ void red4(float* p, float a, float b, float c, float d) {
    asm volatile("red.global.add.v4.f32 [%0], {%1,%2,%3,%4};"
                 :: "l"(p), "f"(a), "f"(b), "f"(c), "f"(d) : "memory");
}

__global__ void init_kernel() {
    int gid = blockIdx.x * 256 + threadIdx.x;
    if (gid < KC * DLAT) g_acc[0].acc[gid] = 0.f;
    if (gid < KC) g_acc[0].cs[gid] = 0.f;
    if (gid == 0) { g_l.loss = 0.f; g_l.dloss = 0.0; }
}

// ---------------------------------------------------------------------------
// Fused k-means iteration + decoder-loss slice.
//  CT_s[j][k] = C[k][j]; phase1 d2 GEMM (f32x2 over k) -> softmax -> r;
//  phase2 acc[wr] += r^T x via red.v4; zeroes acc[zr] for iteration it+1.
// ---------------------------------------------------------------------------
template<bool FROM_ENC, bool DO_LOSS, bool DO_P2>
__global__ __launch_bounds__(NT, 4) void kmeans_iter(
    const float* __restrict__ enc,
    const float4* __restrict__ X, const float4* __restrict__ Dc,
    int decB, int decE, int rd, int wr, int zr)
{
    extern __shared__ float sm[];
    float* x_s   = sm;                   // [TILE][XP]
    float* r_s   = x_s + TILE * XP;      // [TILE][RP]  d2 then r
    float* CT_s  = r_s + TILE * RP;      // [DLAT][CP]
    float* x2_s  = CT_s + DLAT * CP;     // [TILE]
    float* c2_s  = x2_s + TILE;          // [KC]
    float* red_s = c2_s + KC;            // [8]
    float* dec_s = red_s + 8;            // [8]

    const int t = threadIdx.x;
    const int b = blockIdx.x;
    const int row0 = b * TILE;

    // ---- zero the accumulator buffer for iteration it+1 (3-buffer rotation)
    if (DO_P2) {
        int gid = b * NT + t;
        if (gid < KC * DLAT) g_acc[zr].acc[gid] = 0.f;
        if (gid < KC) g_acc[zr].cs[gid] = 0.f;
    }

    // ---- x tile (coalesced)
    for (int i = t; i < TILE * DLAT; i += NT) {
        int r = i >> 6, j = i & 63;
        x_s[r * XP + j] = enc[(row0 + r) * DLAT + j];
    }
    // ---- CT build (transposed store; 4-way conflict is negligible one-time cost)
    if (FROM_ENC) {
        for (int i = t; i < KC * DLAT; i += NT) {
            int k = i >> 6, j = i & 63;
            CT_s[j * CP + k] = enc[i];
        }
    } else {
        for (int i = t; i < KC * DLAT; i += NT) {
            int k = i >> 6, j = i & 63;
            CT_s[j * CP + k] = g_acc[rd].acc[i] * (1.0f / (g_acc[rd].cs[k] + EPSV));
        }
    }

    // ---- decoder loss slice (global loads overlap smem fills)
    {
        float ds0 = 0.f, ds1 = 0.f;
        const int stride = NBLK * NT;
        int i = decB + b * NT + t;
        for (; i + stride < decE; i += 2 * stride) {
            float4 a0 = X[i], b0 = Dc[i];
            float4 a1 = X[i + stride], b1 = Dc[i + stride];
            float d0 = a0.x - b0.x, d1 = a0.y - b0.y, d2 = a0.z - b0.z, d3 = a0.w - b0.w;
            ds0 = fmaf(d0, d0, fmaf(d1, d1, fmaf(d2, d2, fmaf(d3, d3, ds0))));
            float e0 = a1.x - b1.x, e1 = a1.y - b1.y, e2 = a1.z - b1.z, e3 = a1.w - b1.w;
            ds1 = fmaf(e0, e0, fmaf(e1, e1, fmaf(e2, e2, fmaf(e3, e3, ds1))));
        }
        if (i < decE) {
            float4 a0 = X[i], b0 = Dc[i];
            float d0 = a0.x - b0.x, d1 = a0.y - b0.y, d2 = a0.z - b0.z, d3 = a0.w - b0.w;
            ds0 = fmaf(d0, d0, fmaf(d1, d1, fmaf(d2, d2, fmaf(d3, d3, ds0))));
        }
        float ds = ds0 + ds1;
        #pragma unroll
        for (int o = 16; o; o >>= 1) ds += __shfl_xor_sync(0xffffffffu, ds, o);
        if ((t & 31) == 0) dec_s[t >> 5] = ds;
    }
    __syncthreads();

    // ---- |x|^2 (t<64), |c|^2 (64<=t<128), decoder atomic (t==255)
    if (t < TILE) {
        float s = 0.f;
        const float4* xr = (const float4*)&x_s[t * XP];
        #pragma unroll
        for (int q = 0; q < 16; ++q) {
            float4 v = xr[q];
            s = fmaf(v.x, v.x, fmaf(v.y, v.y, fmaf(v.z, v.z, fmaf(v.w, v.w, s))));
        }
        x2_s[t] = s;
    } else if (t < TILE + KC) {
        int k = t - TILE;
        float s = 0.f;
        #pragma unroll
        for (int j = 0; j < DLAT; ++j) {
            float v = CT_s[j * CP + k];
            s = fmaf(v, v, s);
        }
        c2_s[k] = s;
    } else if (t == NT - 1) {
        double s = 0.0;
        #pragma unroll
        for (int w = 0; w < 8; w++) s += (double)dec_s[w];
        atomicAdd(&g_l.dloss, s);
    }
    __syncthreads();

    // ---- phase 1: thread = 2 rows x 8 k, f32x2 over k-pairs, c warp-broadcast
    {
        const int tx = t & 31;        // rows tx, tx+32
        const int ty = t >> 5;        // k0 = ty*8
        const int k0 = ty * 8;
        ull a0[4], a1[4];
        #pragma unroll
        for (int p = 0; p < 4; p++) { a0[p] = 0ull; a1[p] = 0ull; }
        const float* xr0 = &x_s[tx * XP];
        const float* xr1 = &x_s[(tx + 32) * XP];

        #pragma unroll 4
        for (int j4 = 0; j4 < 16; ++j4) {
            float4 xa = *(const float4*)&xr0[j4 * 4];
            float4 xb = *(const float4*)&xr1[j4 * 4];
            #pragma unroll
            for (int jj = 0; jj < 4; ++jj) {
                const float* crow = &CT_s[(j4 * 4 + jj) * CP + k0];
                ulonglong2 cpq = *(const ulonglong2*)crow;
                ulonglong2 crs = *(const ulonglong2*)(crow + 4);
                float s0 = (jj == 0) ? xa.x : (jj == 1) ? xa.y : (jj == 2) ? xa.z : xa.w;
                float s1 = (jj == 0) ? xb.x : (jj == 1) ? xb.y : (jj == 2) ? xb.z : xb.w;
                ull xd0 = pack2(s0, s0), xd1 = pack2(s1, s1);
                a0[0] = ffma2(xd0, cpq.x, a0[0]); a0[1] = ffma2(xd0, cpq.y, a0[1]);
                a0[2] = ffma2(xd0, crs.x, a0[2]); a0[3] = ffma2(xd0, crs.y, a0[3]);
                a1[0] = ffma2(xd1, cpq.x, a1[0]); a1[1] = ffma2(xd1, cpq.y, a1[1]);
                a1[2] = ffma2(xd1, crs.x, a1[2]); a1[3] = ffma2(xd1, crs.y, a1[3]);
            }
        }
        float x20 = x2_s[tx], x21 = x2_s[tx + 32];
        #pragma unroll
        for (int p = 0; p < 4; p++) {
            float c2a = c2_s[k0 + 2 * p], c2b = c2_s[k0 + 2 * p + 1];
            float da, db;
            unpack2(a0[p], da, db);
            *(float2*)&r_s[tx * RP + k0 + 2 * p] =
                make_float2(fmaxf(fmaf(-2.f, da, x20 + c2a), 0.f),
                            fmaxf(fmaf(-2.f, db, x20 + c2b), 0.f));
            unpack2(a1[p], da, db);
            *(float2*)&r_s[(tx + 32) * RP + k0 + 2 * p] =
                make_float2(fmaxf(fmaf(-2.f, da, x21 + c2a), 0.f),
                            fmaxf(fmaf(-2.f, db, x21 + c2b), 0.f));
        }
    }
    __syncthreads();

    // ---- softmax: thread = (row = t>>2, k-quarter = t&3), quad combine via shfl
    {
        const int row = t >> 2, q = t & 3;
        float* rp = &r_s[row * RP + q * 16];
        float d2v[16];
        #pragma unroll
        for (int v4i = 0; v4i < 4; ++v4i) {
            float4 v = *(const float4*)&rp[v4i * 4];
            d2v[4 * v4i] = v.x; d2v[4 * v4i + 1] = v.y;
            d2v[4 * v4i + 2] = v.z; d2v[4 * v4i + 3] = v.w;
        }
        float m = d2v[0];
        #pragma unroll
        for (int k = 1; k < 16; ++k) m = fminf(m, d2v[k]);
        m = fminf(m, __shfl_xor_sync(0xffffffffu, m, 1));
        m = fminf(m, __shfl_xor_sync(0xffffffffu, m, 2));
        float Z = 0.f, ln = 0.f;
        #pragma unroll
        for (int k = 0; k < 16; ++k) {
            float e = __expf(m - d2v[k]);
            if (DO_LOSS) ln = fmaf(e, d2v[k], ln);
            Z += e;
            d2v[k] = e;
        }
        Z += __shfl_xor_sync(0xffffffffu, Z, 1);
        Z += __shfl_xor_sync(0xffffffffu, Z, 2);
        float invZ = 1.0f / Z;
        if (DO_P2) {
            #pragma unroll
            for (int v4i = 0; v4i < 4; ++v4i)
                *(float4*)&rp[v4i * 4] =
                    make_float4(d2v[4 * v4i] * invZ, d2v[4 * v4i + 1] * invZ,
                                d2v[4 * v4i + 2] * invZ, d2v[4 * v4i + 3] * invZ);
        }
        if (DO_LOSS) {
            ln += __shfl_xor_sync(0xffffffffu, ln, 1);
            ln += __shfl_xor_sync(0xffffffffu, ln, 2);
            float lrow = ln * invZ * 0.25f;   // 4 lanes share each row
            #pragma unroll
            for (int o = 16; o; o >>= 1) lrow += __shfl_xor_sync(0xffffffffu, lrow, o);
            if ((t & 31) == 0) red_s[t >> 5] = lrow;
        }
    }
    __syncthreads();
    if (DO_LOSS && t == 0) {
        float s = 0.f;
        #pragma unroll
        for (int w = 0; w < 8; w++) s += red_s[w];
        atomicAdd(&g_l.loss, s);
    }
    if (!DO_P2) return;

    // ---- phase 2: thread = 4j x 4k; r warp-broadcast, f32x2 over k-pairs
    {
        const int jg = t & 15, kq = t >> 4;
        const int j0 = jg * 4, k0 = kq * 4;
        ull a00 = 0, a01 = 0, a10 = 0, a11 = 0, a20 = 0, a21 = 0, a30 = 0, a31 = 0;
        ull cs0 = 0, cs1 = 0;

        #pragma unroll 4
        for (int row = 0; row < TILE; ++row) {
            ulonglong2 rv = *(const ulonglong2*)&r_s[row * RP + k0];
            float4 xv = *(const float4*)&x_s[row * XP + j0];
            ull xd0 = pack2(xv.x, xv.x), xd1 = pack2(xv.y, xv.y);
            ull xd2 = pack2(xv.z, xv.z), xd3 = pack2(xv.w, xv.w);
            a00 = ffma2(xd0, rv.x, a00); a01 = ffma2(xd0, rv.y, a01);
            a10 = ffma2(xd1, rv.x, a10); a11 = ffma2(xd1, rv.y, a11);
            a20 = ffma2(xd2, rv.x, a20); a21 = ffma2(xd2, rv.y, a21);
            a30 = ffma2(xd3, rv.x, a30); a31 = ffma2(xd3, rv.y, a31);
            if (jg == 0) { cs0 = add2(cs0, rv.x); cs1 = add2(cs1, rv.y); }
        }
        float w0[4], w1[4], w2[4], w3[4];
        unpack2(a00, w0[0], w0[1]); unpack2(a01, w0[2], w0[3]);
        unpack2(a10, w1[0], w1[1]); unpack2(a11, w1[2], w1[3]);
        unpack2(a20, w2[0], w2[1]); unpack2(a21, w2[2], w2[3]);
        unpack2(a30, w3[0], w3[1]); unpack2(a31, w3[2], w3[3]);
        #pragma unroll
        for (int kk = 0; kk < 4; ++kk)
            red4(&g_acc[wr].acc[(k0 + kk) * DLAT + j0], w0[kk], w1[kk], w2[kk], w3[kk]);
        if (jg == 0) {
            float c0, c1, c2, c3;
            unpack2(cs0, c0, c1); unpack2(cs1, c2, c3);
            red4(&g_acc[wr].cs[k0], c0, c1, c2, c3);
        }
    }
}

__global__ void final_kernel(float* out) {
    out[0] = (float)(g_l.dloss * (1.0 / ((double)NROWS * (double)DDATA)))
           + ALPHA * (g_l.loss / (float)NROWS);
}

// ---------------------------------------------------------------------------
extern "C" void kernel_launch(void* const* d_in, const int* in_sizes, int n_in,
                              void* d_out, int out_size) {
    const float* X   = (const float*)d_in[0];
    const float* enc = (const float*)d_in[1];
    const float* dec = (const float*)d_in[2];
    float* out = (float*)d_out;
    const float4* X4 = (const float4*)X;
    const float4* D4 = (const float4*)dec;

    const size_t smem = (size_t)(TILE * XP + TILE * RP + DLAT * CP
                                 + TILE + KC + 8 + 8) * sizeof(float);
    cudaFuncSetAttribute(kmeans_iter<true,  false, true >,
                         cudaFuncAttributeMaxDynamicSharedMemorySize, (int)smem);
    cudaFuncSetAttribute(kmeans_iter<false, false, true >,
                         cudaFuncAttributeMaxDynamicSharedMemorySize, (int)smem);
    cudaFuncSetAttribute(kmeans_iter<false, true,  false>,
                         cudaFuncAttributeMaxDynamicSharedMemorySize, (int)smem);

    const int N4 = NROWS * DDATA / 4;
    auto chunkB = [&](int it) { return (int)((long long)it * N4 / NITER); };

    init_kernel<<<17, 256>>>();

    // iter 0: C from enc; writes buf0 (pre-zeroed by init), zeroes buf1
    kmeans_iter<true, false, true><<<NBLK, NT, smem>>>(
        enc, X4, D4, chunkB(0), chunkB(1), 0, 0, 1);

    // iters 1..8: rd=(it-1)%3, wr=it%3 (zeroed last iter), zero (it+1)%3
    for (int it = 1; it <= 8; ++it) {
        kmeans_iter<false, false, true><<<NBLK, NT, smem>>>(
            enc, X4, D4, chunkB(it), chunkB(it + 1),
            (it - 1) % 3, it % 3, (it + 1) % 3);
    }

    // iter 9: loss only
    kmeans_iter<false, true, false><<<NBLK, NT, smem>>>(
        enc, X4, D4, chunkB(9), chunkB(10), 2, 0, 0);

    final_kernel<<<1, 1>>>(out);
}

// round 7
// speedup vs baseline: 2.0356x; 2.0356x over previous
#include <cuda_runtime.h>
#include <cuda_bf16.h>
#include <cstdint>

#define NROWS 65536
#define DDATA 512
#define DLAT  64
#define KC    64
#define TILE  128
#define NT    256
#define NBLK  (NROWS / TILE)     // 512
#define NITER 10
#define EPSV  1e-8f
#define ALPHA 0.001f

// byte strides (padded for conflict-free ldmatrix: stride mod 128B == 16)
#define XSTR 144                 // 72 bf16 per row
#define CSTR 144
#define RSTR 272                 // 136 bf16 per row

// smem byte offsets
#define OFF_XH  0                // [128][72] bf16
#define OFF_XL  18432
#define OFF_CH  36864            // [64][72] bf16
#define OFF_CL  46080
#define OFF_RH  55296            // [64 clusters][136 rows] bf16
#define OFF_RL  72704
#define OFF_X2  90112            // [128] f32
#define OFF_C2  90624            // [64] f32
#define OFF_DEC 90880            // [8] f32
#define OFF_RED 90912            // [8] f32
#define SMEM_SZ 90944

struct AccBuf { float acc[KC * DLAT]; float cs[KC]; };
__device__ AccBuf g_acc[3];
struct LossBuf { float loss; float pad; double dloss; };
__device__ LossBuf g_l;

// ---------------- helpers ----------------
__device__ __forceinline__ uint32_t smem_u32(const void* p) {
    uint32_t a;
    asm("{ .reg .u64 t; cvta.to.shared.u64 t, %1; cvt.u32.u64 %0, t; }"
        : "=r"(a) : "l"(p));
    return a;
}
__device__ __forceinline__ void ldm4(uint32_t* r, uint32_t a) {
    asm volatile("ldmatrix.sync.aligned.m8n8.x4.shared.b16 {%0,%1,%2,%3}, [%4];"
        : "=r"(r[0]), "=r"(r[1]), "=r"(r[2]), "=r"(r[3]) : "r"(a));
}
__device__ __forceinline__ void ldm2(uint32_t* r, uint32_t a) {
    asm volatile("ldmatrix.sync.aligned.m8n8.x2.shared.b16 {%0,%1}, [%2];"
        : "=r"(r[0]), "=r"(r[1]) : "r"(a));
}
__device__ __forceinline__ void ldm2t(uint32_t* r, uint32_t a) {
    asm volatile("ldmatrix.sync.aligned.m8n8.x2.trans.shared.b16 {%0,%1}, [%2];"
        : "=r"(r[0]), "=r"(r[1]) : "r"(a));
}
__device__ __forceinline__ void mma16816(float* d, const uint32_t* a, const uint32_t* b) {
    asm volatile("mma.sync.aligned.m16n8k16.row.col.f32.bf16.bf16.f32 "
        "{%0,%1,%2,%3}, {%4,%5,%6,%7}, {%8,%9}, {%0,%1,%2,%3};"
        : "+f"(d[0]), "+f"(d[1]), "+f"(d[2]), "+f"(d[3])
        : "r"(a[0]), "r"(a[1]), "r"(a[2]), "r"(a[3]), "r"(b[0]), "r"(b[1]));
}
__device__ __forceinline__ void red2(float* p, float a, float b) {
    asm volatile("red.global.add.v2.f32 [%0], {%1,%2};"
                 :: "l"(p), "f"(a), "f"(b) : "memory");
}
__device__ __forceinline__ void split2(float v, uint16_t& h, uint16_t& l) {
    __nv_bfloat16 hb = __float2bfloat16(v);
    __nv_bfloat16 lb = __float2bfloat16(v - __bfloat162float(hb));
    h = __bfloat16_as_ushort(hb);
    l = __bfloat16_as_ushort(lb);
}

__global__ void init_kernel() {
    int gid = blockIdx.x * 256 + threadIdx.x;
    if (gid < KC * DLAT) g_acc[0].acc[gid] = 0.f;
    if (gid < KC) g_acc[0].cs[gid] = 0.f;
    if (gid == 0) { g_l.loss = 0.f; g_l.dloss = 0.0; }
}

// ---------------------------------------------------------------------------
// Fused k-means iteration on HMMA (mma.sync bf16, hi/lo split) + decoder slice.
// ---------------------------------------------------------------------------
template<bool FROM_ENC, bool DO_LOSS, bool DO_P2>
__global__ __launch_bounds__(NT, 2) void kmeans_iter(
    const float* __restrict__ enc,
    const float4* __restrict__ X, const float4* __restrict__ Dc,
    int decB, int decE, int rd, int wr, int zr)
{
    extern __shared__ __align__(128) char smem[];
    const uint32_t sb = smem_u32(smem);
    const int t = threadIdx.x, b = blockIdx.x;
    const int wid = t >> 5, lane = t & 31;
    float* x2_s  = (float*)(smem + OFF_X2);
    float* c2_s  = (float*)(smem + OFF_C2);
    float* dec_s = (float*)(smem + OFF_DEC);
    float* red_s = (float*)(smem + OFF_RED);

    // ---- zero accumulator buffer for iteration it+1 (3-buffer rotation)
    if (DO_P2) {
        int gid = b * NT + t;
        if (gid < KC * DLAT) g_acc[zr].acc[gid] = 0.f;
        if (gid < KC) g_acc[zr].cs[gid] = 0.f;
    }

    // ---- x tile -> bf16 hi/lo + x2
    {
        int row = t >> 1, jh = (t & 1) * 32;
        const float4* src = (const float4*)&enc[(b * TILE + row) * DLAT + jh];
        char* xh = smem + OFF_XH + row * XSTR + jh * 2;
        char* xl = smem + OFF_XL + row * XSTR + jh * 2;
        float x2p = 0.f;
        #pragma unroll
        for (int q = 0; q < 8; ++q) {
            float4 v = src[q];
            x2p = fmaf(v.x, v.x, fmaf(v.y, v.y, fmaf(v.z, v.z, fmaf(v.w, v.w, x2p))));
            uint16_t h0, l0, h1, l1, h2, l2, h3, l3;
            split2(v.x, h0, l0); split2(v.y, h1, l1);
            split2(v.z, h2, l2); split2(v.w, h3, l3);
            *(uint32_t*)(xh + q * 8)     = ((uint32_t)h1 << 16) | h0;
            *(uint32_t*)(xh + q * 8 + 4) = ((uint32_t)h3 << 16) | h2;
            *(uint32_t*)(xl + q * 8)     = ((uint32_t)l1 << 16) | l0;
            *(uint32_t*)(xl + q * 8 + 4) = ((uint32_t)l3 << 16) | l2;
        }
        x2p += __shfl_xor_sync(0xffffffffu, x2p, 1);
        if ((t & 1) == 0) x2_s[row] = x2p;
    }

    // ---- C tile -> bf16 hi/lo + c2
    {
        int k = t >> 2, jq = t & 3;
        float inv = 1.f;
        const float* srcC;
        if (FROM_ENC) srcC = &enc[k * DLAT];
        else { inv = 1.0f / (g_acc[rd].cs[k] + EPSV); srcC = &g_acc[rd].acc[k * DLAT]; }
        char* ch = smem + OFF_CH + k * CSTR;
        char* cl = smem + OFF_CL + k * CSTR;
        float c2p = 0.f;
        #pragma unroll
        for (int q = 0; q < 4; ++q) {
            int j = jq * 16 + q * 4;
            float4 v = *(const float4*)&srcC[j];
            v.x *= inv; v.y *= inv; v.z *= inv; v.w *= inv;
            c2p = fmaf(v.x, v.x, fmaf(v.y, v.y, fmaf(v.z, v.z, fmaf(v.w, v.w, c2p))));
            uint16_t h0, l0, h1, l1, h2, l2, h3, l3;
            split2(v.x, h0, l0); split2(v.y, h1, l1);
            split2(v.z, h2, l2); split2(v.w, h3, l3);
            *(uint32_t*)(ch + j * 2)     = ((uint32_t)h1 << 16) | h0;
            *(uint32_t*)(ch + j * 2 + 4) = ((uint32_t)h3 << 16) | h2;
            *(uint32_t*)(cl + j * 2)     = ((uint32_t)l1 << 16) | l0;
            *(uint32_t*)(cl + j * 2 + 4) = ((uint32_t)l3 << 16) | l2;
        }
        c2p += __shfl_xor_sync(0xffffffffu, c2p, 1);
        c2p += __shfl_xor_sync(0xffffffffu, c2p, 2);
        if (jq == 0) c2_s[k] = c2p;
    }

    // ---- decoder-loss slice
    {
        float ds = 0.f;
        const int stride = NBLK * NT;
        for (int i = decB + b * NT + t; i < decE; i += stride) {
            float4 a0 = X[i], b0 = Dc[i];
            float d0 = a0.x - b0.x, d1 = a0.y - b0.y, d2 = a0.z - b0.z, d3 = a0.w - b0.w;
            ds = fmaf(d0, d0, fmaf(d1, d1, fmaf(d2, d2, fmaf(d3, d3, ds))));
        }
        #pragma unroll
        for (int o = 16; o; o >>= 1) ds += __shfl_xor_sync(0xffffffffu, ds, o);
        if (lane == 0) dec_s[wid] = ds;
    }
    __syncthreads();                                   // S1

    if (t == 0) {
        double s = 0.0;
        #pragma unroll
        for (int w = 0; w < 8; w++) s += (double)dec_s[w];
        atomicAdd(&g_l.dloss, s);
    }

    // ldmatrix per-lane address components
    const int g = lane >> 3, ri = lane & 7;
    const int bl = lane & 15, bh = bl >> 3, bri = bl & 7;

    // ======== phase 1: D[row][cluster] = x . c  (3-term bf16 split) ========
    float D[8][4];
    #pragma unroll
    for (int nt = 0; nt < 8; ++nt)
        #pragma unroll
        for (int i = 0; i < 4; ++i) D[nt][i] = 0.f;
    {
        const int wm = wid * 16;
        uint32_t aH = sb + OFF_XH + (uint32_t)(wm + (g & 1) * 8 + ri) * XSTR
                    + (uint32_t)((g >> 1) * 16);
        uint32_t aL = aH + (OFF_XL - OFF_XH);
        uint32_t bH = sb + OFF_CH + (uint32_t)bri * CSTR + (uint32_t)(bh * 16);
        uint32_t bL = bH + (OFF_CL - OFF_CH);
        #pragma unroll
        for (int ks = 0; ks < 4; ++ks) {
            uint32_t ah[4], al[4];
            ldm4(ah, aH + ks * 32);
            ldm4(al, aL + ks * 32);
            #pragma unroll
            for (int nt = 0; nt < 8; ++nt) {
                uint32_t bf[2];
                ldm2(bf, bH + nt * (8 * CSTR) + ks * 32);
                mma16816(D[nt], ah, bf);
                mma16816(D[nt], al, bf);
                ldm2(bf, bL + nt * (8 * CSTR) + ks * 32);
                mma16816(D[nt], ah, bf);
            }
        }
    }

    // ======== epilogue 1: d2, softmax, r stores, colsum ========
    {
        const int wm = wid * 16;
        const int qr = lane >> 2, qc = lane & 3;
        const int r0 = wm + qr, r1 = r0 + 8;
        const float x20 = x2_s[r0], x21 = x2_s[r1];
        float mn0 = 1e30f, mn1 = 1e30f;
        #pragma unroll
        for (int nt = 0; nt < 8; ++nt) {
            int c0 = nt * 8 + 2 * qc;
            float ca = c2_s[c0], cb = c2_s[c0 + 1];
            float d00 = fmaxf(x20 + ca - 2.f * D[nt][0], 0.f);
            float d01 = fmaxf(x20 + cb - 2.f * D[nt][1], 0.f);
            float d10 = fmaxf(x21 + ca - 2.f * D[nt][2], 0.f);
            float d11 = fmaxf(x21 + cb - 2.f * D[nt][3], 0.f);
            D[nt][0] = d00; D[nt][1] = d01; D[nt][2] = d10; D[nt][3] = d11;
            mn0 = fminf(mn0, fminf(d00, d01));
            mn1 = fminf(mn1, fminf(d10, d11));
        }
        mn0 = fminf(mn0, __shfl_xor_sync(0xffffffffu, mn0, 1));
        mn0 = fminf(mn0, __shfl_xor_sync(0xffffffffu, mn0, 2));
        mn1 = fminf(mn1, __shfl_xor_sync(0xffffffffu, mn1, 1));
        mn1 = fminf(mn1, __shfl_xor_sync(0xffffffffu, mn1, 2));
        float Z0 = 0.f, Z1 = 0.f, ln0 = 0.f, ln1 = 0.f;
        #pragma unroll
        for (int nt = 0; nt < 8; ++nt) {
            float e00 = __expf(mn0 - D[nt][0]);
            float e01 = __expf(mn0 - D[nt][1]);
            float e10 = __expf(mn1 - D[nt][2]);
            float e11 = __expf(mn1 - D[nt][3]);
            if (DO_LOSS) {
                ln0 = fmaf(e00, D[nt][0], fmaf(e01, D[nt][1], ln0));
                ln1 = fmaf(e10, D[nt][2], fmaf(e11, D[nt][3], ln1));
            }
            Z0 += e00 + e01; Z1 += e10 + e11;
            D[nt][0] = e00; D[nt][1] = e01; D[nt][2] = e10; D[nt][3] = e11;
        }
        Z0 += __shfl_xor_sync(0xffffffffu, Z0, 1);
        Z0 += __shfl_xor_sync(0xffffffffu, Z0, 2);
        Z1 += __shfl_xor_sync(0xffffffffu, Z1, 1);
        Z1 += __shfl_xor_sync(0xffffffffu, Z1, 2);
        const float iZ0 = 1.0f / Z0, iZ1 = 1.0f / Z1;

        if (DO_P2) {
            #pragma unroll
            for (int nt = 0; nt < 8; ++nt) {
                int c0 = nt * 8 + 2 * qc;
                float r00 = D[nt][0] * iZ0, r01 = D[nt][1] * iZ0;
                float r10 = D[nt][2] * iZ1, r11 = D[nt][3] * iZ1;
                uint16_t h, l;
                char* pH0 = smem + OFF_RH + c0 * RSTR;
                char* pL0 = smem + OFF_RL + c0 * RSTR;
                split2(r00, h, l);
                *(uint16_t*)(pH0 + r0 * 2) = h; *(uint16_t*)(pL0 + r0 * 2) = l;
                split2(r10, h, l);
                *(uint16_t*)(pH0 + r1 * 2) = h; *(uint16_t*)(pL0 + r1 * 2) = l;
                split2(r01, h, l);
                *(uint16_t*)(pH0 + RSTR + r0 * 2) = h; *(uint16_t*)(pL0 + RSTR + r0 * 2) = l;
                split2(r11, h, l);
                *(uint16_t*)(pH0 + RSTR + r1 * 2) = h; *(uint16_t*)(pL0 + RSTR + r1 * 2) = l;
                // colsum over this warp's 16 rows
                float cs0 = r00 + r10, cs1 = r01 + r11;
                cs0 += __shfl_xor_sync(0xffffffffu, cs0, 4);
                cs0 += __shfl_xor_sync(0xffffffffu, cs0, 8);
                cs0 += __shfl_xor_sync(0xffffffffu, cs0, 16);
                cs1 += __shfl_xor_sync(0xffffffffu, cs1, 4);
                cs1 += __shfl_xor_sync(0xffffffffu, cs1, 8);
                cs1 += __shfl_xor_sync(0xffffffffu, cs1, 16);
                if (qr == 0) red2(&g_acc[wr].cs[c0], cs0, cs1);
            }
        }
        if (DO_LOSS) {
            ln0 += __shfl_xor_sync(0xffffffffu, ln0, 1);
            ln0 += __shfl_xor_sync(0xffffffffu, ln0, 2);
            ln1 += __shfl_xor_sync(0xffffffffu, ln1, 1);
            ln1 += __shfl_xor_sync(0xffffffffu, ln1, 2);
            float lrow = (ln0 * iZ0 + ln1 * iZ1) * 0.25f;
            #pragma unroll
            for (int o = 16; o; o >>= 1) lrow += __shfl_xor_sync(0xffffffffu, lrow, o);
            if (lane == 0) red_s[wid] = lrow;
        }
    }
    __syncthreads();                                   // S2

    if (DO_LOSS && t == 0) {
        float s = 0.f;
        #pragma unroll
        for (int w = 0; w < 8; w++) s += red_s[w];
        atomicAdd(&g_l.loss, s);
    }
    if (!DO_P2) return;

    // ======== phase 2: Cacc[k][j] += sum_rows r[row][k] x[row][j] ========
    float E[4][4];
    #pragma unroll
    for (int nt = 0; nt < 4; ++nt)
        #pragma unroll
        for (int i = 0; i < 4; ++i) E[nt][i] = 0.f;
    const int cm = (wid & 3) * 16, jn = (wid >> 2) * 32;
    {
        uint32_t aH = sb + OFF_RH + (uint32_t)(cm + (g & 1) * 8 + ri) * RSTR
                    + (uint32_t)((g >> 1) * 16);
        uint32_t aL = aH + (OFF_RL - OFF_RH);
        uint32_t bH = sb + OFF_XH + (uint32_t)(bh * 8 + bri) * XSTR + (uint32_t)(jn * 2);
        uint32_t bL = bH + (OFF_XL - OFF_XH);
        #pragma unroll
        for (int ks = 0; ks < 8; ++ks) {
            uint32_t ah[4], al[4];
            ldm4(ah, aH + ks * 32);
            ldm4(al, aL + ks * 32);
            #pragma unroll
            for (int nt = 0; nt < 4; ++nt) {
                uint32_t bf[2];
                ldm2t(bf, bH + ks * (16 * XSTR) + nt * 16);
                mma16816(E[nt], ah, bf);
                mma16816(E[nt], al, bf);
                ldm2t(bf, bL + ks * (16 * XSTR) + nt * 16);
                mma16816(E[nt], ah, bf);
            }
        }
    }
    // epilogue 2: red.v2 straight into global accumulator
    {
        const int qr = lane >> 2, qc = lane & 3;
        float* acc = g_acc[wr].acc;
        #pragma unroll
        for (int nt = 0; nt < 4; ++nt) {
            int j = jn + nt * 8 + 2 * qc;
            red2(&acc[(cm + qr) * DLAT + j], E[nt][0], E[nt][1]);
            red2(&acc[(cm + qr + 8) * DLAT + j], E[nt][2], E[nt][3]);
        }
    }
}

__global__ void final_kernel(float* out) {
    out[0] = (float)(g_l.dloss * (1.0 / ((double)NROWS * (double)DDATA)))
           + ALPHA * (g_l.loss / (float)NROWS);
}

// ---------------------------------------------------------------------------
extern "C" void kernel_launch(void* const* d_in, const int* in_sizes, int n_in,
                              void* d_out, int out_size) {
    const float* X   = (const float*)d_in[0];
    const float* enc = (const float*)d_in[1];
    const float* dec = (const float*)d_in[2];
    float* out = (float*)d_out;
    const float4* X4 = (const float4*)X;
    const float4* D4 = (const float4*)dec;

    cudaFuncSetAttribute(kmeans_iter<true,  false, true >,
                         cudaFuncAttributeMaxDynamicSharedMemorySize, SMEM_SZ);
    cudaFuncSetAttribute(kmeans_iter<false, false, true >,
                         cudaFuncAttributeMaxDynamicSharedMemorySize, SMEM_SZ);
    cudaFuncSetAttribute(kmeans_iter<false, true,  false>,
                         cudaFuncAttributeMaxDynamicSharedMemorySize, SMEM_SZ);

    const int N4 = NROWS * DDATA / 4;
    auto chunkB = [&](int it) { return (int)((long long)it * N4 / NITER); };

    init_kernel<<<17, 256>>>();

    // iter 0: C from enc; writes buf0 (pre-zeroed), zeroes buf1
    kmeans_iter<true, false, true><<<NBLK, NT, SMEM_SZ>>>(
        enc, X4, D4, chunkB(0), chunkB(1), 0, 0, 1);

    for (int it = 1; it <= 8; ++it) {
        kmeans_iter<false, false, true><<<NBLK, NT, SMEM_SZ>>>(
            enc, X4, D4, chunkB(it), chunkB(it + 1),
            (it - 1) % 3, it % 3, (it + 1) % 3);
    }

    // iter 9: loss only
    kmeans_iter<false, true, false><<<NBLK, NT, SMEM_SZ>>>(
        enc, X4, D4, chunkB(9), chunkB(10), 2, 0, 0);

    final_kernel<<<1, 1>>>(out);
}